// round 14
// baseline (speedup 1.0000x reference)
#include <cuda_runtime.h>
#include <cuda_fp16.h>
#include <cstdint>

// ============================================================================
// SpatialGAT on GB300 — round 14: 2-kernel pipeline (round 13 + fixed pack bound)
//
// Kernel 1 (transform): per CTA (i-tile 128, head):
//   A. pack 32-row slice of adj -> g_adjb (ballot; 1024 warp-units = 32 rows)
//   B. h-tile = x @ W via HMMA (x and W converted f32->f16 inline)
//   C. epilogue: write g_hf f16; s,d dots from f32 accumulators (quad shfl)
//      -> R = exp(-.8s), Q = exp(d), Q2 = exp(.2d) tables
// Kernel 2 (aggregate): w'_ij = bit * max(Q_j, R_i*Q2_j) in mma fragments;
//   B cp.async double buffer; Z via ones-mma on f16 pair-sums; acc/Z + bias.
// ============================================================================

#define NN      8192
#define FOUT    256
#define FIN     256
#define HEADS   4
#define NEG_SLOPE 0.2f
#define BI      128
#define BJ      128
#define NCHUNK  (NN / BJ)
#define NWORDS  (NN / 32)
#define NBLK64  (NN / 64)

__device__ __half   g_hf[NN * FOUT];
__device__ __half   g_RT[HEADS * NN];                 // exp(-0.8 s), head-major
__device__ uint32_t g_Qsw [HEADS * NBLK64 * 32];      // kk-swizzled f16 pairs
__device__ uint32_t g_Q2sw[HEADS * NBLK64 * 32];
__device__ unsigned g_adjb[NN * NWORDS];

// ---------------------------------------------------------------------------
__device__ __forceinline__ uint32_t smem_u32(const void* p) {
    uint32_t a;
    asm("{ .reg .u64 t; cvta.to.shared.u64 t, %1; cvt.u32.u64 %0, t; }"
        : "=r"(a) : "l"(p));
    return a;
}
__device__ __forceinline__ uint32_t hmul2_(uint32_t a, uint32_t b) {
    uint32_t d; asm("mul.f16x2 %0, %1, %2;" : "=r"(d) : "r"(a), "r"(b)); return d;
}
__device__ __forceinline__ uint32_t hmax2_(uint32_t a, uint32_t b) {
    uint32_t d; asm("max.f16x2 %0, %1, %2;" : "=r"(d) : "r"(a), "r"(b)); return d;
}
__device__ __forceinline__ uint32_t hadd2_(uint32_t a, uint32_t b) {
    uint32_t d; asm("add.f16x2 %0, %1, %2;" : "=r"(d) : "r"(a), "r"(b)); return d;
}
__device__ __forceinline__ uint32_t splat16(unsigned short h) {
    uint32_t r; asm("mov.b32 %0, {%1, %1};" : "=r"(r) : "h"(h)); return r;
}
__device__ __forceinline__ uint32_t bfe1s(uint32_t a, int pos) {
    uint32_t d; asm("bfe.s32 %0, %1, %2, 1;" : "=r"(d) : "r"(a), "r"(pos)); return d;
}
__device__ __forceinline__ uint32_t lop_mix(uint32_t t0, uint32_t t1) {
    uint32_t d;
    asm("lop3.b32 %0, %1, %2, 0x0000FFFF, 0xE4;" : "=r"(d) : "r"(t0), "r"(t1));
    return d;
}
__device__ __forceinline__ void ldsm_x4(uint32_t& r0, uint32_t& r1, uint32_t& r2,
                                        uint32_t& r3, uint32_t addr) {
    asm volatile("ldmatrix.sync.aligned.m8n8.x4.shared.b16 {%0,%1,%2,%3}, [%4];"
                 : "=r"(r0), "=r"(r1), "=r"(r2), "=r"(r3) : "r"(addr));
}
__device__ __forceinline__ void ldsm_x4_t(uint32_t& r0, uint32_t& r1, uint32_t& r2,
                                          uint32_t& r3, uint32_t addr) {
    asm volatile("ldmatrix.sync.aligned.m8n8.x4.trans.shared.b16 {%0,%1,%2,%3}, [%4];"
                 : "=r"(r0), "=r"(r1), "=r"(r2), "=r"(r3) : "r"(addr));
}
__device__ __forceinline__ void mma16816(float* c, uint32_t a0, uint32_t a1,
                                         uint32_t a2, uint32_t a3,
                                         uint32_t b0, uint32_t b1) {
    asm volatile(
        "mma.sync.aligned.m16n8k16.row.col.f32.f16.f16.f32 "
        "{%0,%1,%2,%3}, {%4,%5,%6,%7}, {%8,%9}, {%0,%1,%2,%3};"
        : "+f"(c[0]), "+f"(c[1]), "+f"(c[2]), "+f"(c[3])
        : "r"(a0), "r"(a1), "r"(a2), "r"(a3), "r"(b0), "r"(b1));
}
__device__ __forceinline__ void cp_async16(uint32_t dst, const void* src) {
    unsigned long long g;
    asm("cvta.to.global.u64 %0, %1;" : "=l"(g) : "l"(src));
    asm volatile("cp.async.ca.shared.global [%0], [%1], 16;" :: "r"(dst), "l"(g));
}
__device__ __forceinline__ void cp_commit() {
    asm volatile("cp.async.commit_group;" ::: "memory");
}
__device__ __forceinline__ void cp_wait_all() {
    asm volatile("cp.async.wait_group 0;" ::: "memory");
}
#define SWZ(off) ((off) ^ (((off) >> 3) & 0x70))

// ---------------------------------------------------------------------------
// helper: emit R/Q/Q2 table entries for node n, head h
// ---------------------------------------------------------------------------
__device__ __forceinline__ void store_tables(int h, int n, float s, float d) {
    g_RT[h * NN + n] = __float2half_rn(expf(-0.8f * s));
    int blk = n >> 6, c = n & 63;
    int kk = c >> 4, wi = c & 15;
    int m2 = wi >> 1, hs = wi & 1;
    size_t widx = ((size_t)(h * NBLK64 + blk) * 32 + m2 * 4 + kk) * 2 + hs;
    ((__half*)g_Qsw )[widx] = __float2half_rn(expf(d));
    ((__half*)g_Q2sw)[widx] = __float2half_rn(expf(NEG_SLOPE * d));
}

// ---------------------------------------------------------------------------
// Kernel 1: fused pack + transform + tables. grid (64, 4), 256 threads.
// ---------------------------------------------------------------------------
__global__ void __launch_bounds__(256) transform_kernel(
        const float* __restrict__ x, const float* __restrict__ W,
        const int* __restrict__ adj,
        const float* __restrict__ a_src, const float* __restrict__ a_dst) {
    __shared__ __align__(16) unsigned char ts[16384 + 8192];
    const uint32_t sbx = smem_u32(ts);
    const uint32_t sbw = sbx + 16384;
    const int tid = threadIdx.x;
    const int lane = tid & 31, wid = tid >> 5;
    const int i0 = blockIdx.x * 128;
    const int head = blockIdx.y;
    const int n0 = head * 64;

    // ---- Phase A: pack 32-row adj slice (rows 32*cid .. +31) ----
    // 32 rows x 8192 ints = 262144 ints = 1024 warp-units of 256 ints.
    {
        const int cid = blockIdx.y * 64 + blockIdx.x;       // 0..255
        const size_t ibase = (size_t)cid * 32 * NN;
        for (int it = wid; it < 1024; it += 8) {
            const int* p = adj + ibase + (size_t)it * 256;
            unsigned wv[8];
#pragma unroll
            for (int k = 0; k < 8; k++) {
                int v = p[k * 32 + lane];
                wv[k] = __ballot_sync(0xFFFFFFFFu, v != 0);
            }
            if (lane == 0) {
                size_t wb = (size_t)cid * 8192 + (size_t)it * 8;
                *(uint4*)&g_adjb[wb]     = make_uint4(wv[0], wv[1], wv[2], wv[3]);
                *(uint4*)&g_adjb[wb + 4] = make_uint4(wv[4], wv[5], wv[6], wv[7]);
            }
        }
    }

    // ---- Phase B: GEMM h-tile = x @ W ----
    const int arow = (lane & 7) + ((lane >> 3) & 1) * 8;
    const uint32_t a_base = (uint32_t)((wid * 16 + arow) * 128 + (lane >> 4) * 16);
    const int brow = (lane & 7) + ((lane >> 3) & 1) * 8;
    const int bsel = (lane >> 4) & 1;
    const int qrow = lane >> 2, qcol = (lane & 3) * 2;

    float acc[8][4];
#pragma unroll
    for (int nt = 0; nt < 8; nt++)
#pragma unroll
        for (int c = 0; c < 4; c++) acc[nt][c] = 0.f;

    for (int kc = 0; kc < 4; kc++) {
        const int k0 = kc * 64;
#pragma unroll
        for (int u = 0; u < 4; u++) {
            int unit = tid + u * 256;
            int row = unit >> 3, seg = unit & 7;
            const float* xp = &x[(size_t)(i0 + row) * FIN + k0 + seg * 8];
            float4 f0 = *(const float4*)xp;
            float4 f1 = *(const float4*)(xp + 4);
            __half2 h0 = __floats2half2_rn(f0.x, f0.y);
            __half2 h1 = __floats2half2_rn(f0.z, f0.w);
            __half2 h2 = __floats2half2_rn(f1.x, f1.y);
            __half2 h3 = __floats2half2_rn(f1.z, f1.w);
            uint4 v;
            v.x = *(uint32_t*)&h0; v.y = *(uint32_t*)&h1;
            v.z = *(uint32_t*)&h2; v.w = *(uint32_t*)&h3;
            *(uint4*)(ts + SWZ((uint32_t)(row * 128 + seg * 16))) = v;
        }
#pragma unroll
        for (int u = 0; u < 2; u++) {
            int unit = tid + u * 256;
            int row = unit >> 3, seg = unit & 7;
            const float* wp = &W[(size_t)(k0 + row) * FOUT + n0 + seg * 8];
            float4 f0 = *(const float4*)wp;
            float4 f1 = *(const float4*)(wp + 4);
            __half2 h0 = __floats2half2_rn(f0.x, f0.y);
            __half2 h1 = __floats2half2_rn(f0.z, f0.w);
            __half2 h2 = __floats2half2_rn(f1.x, f1.y);
            __half2 h3 = __floats2half2_rn(f1.z, f1.w);
            uint4 v;
            v.x = *(uint32_t*)&h0; v.y = *(uint32_t*)&h1;
            v.z = *(uint32_t*)&h2; v.w = *(uint32_t*)&h3;
            *(uint4*)(ts + 16384 + SWZ((uint32_t)(row * 128 + seg * 16))) = v;
        }
        __syncthreads();
#pragma unroll
        for (int kk = 0; kk < 4; kk++) {
            uint32_t a0, a1, a2, a3;
            ldsm_x4(a0, a1, a2, a3, sbx + SWZ(a_base + kk * 32));
#pragma unroll
            for (int ntp = 0; ntp < 4; ntp++) {
                uint32_t b0, b1, b2, b3;
                ldsm_x4_t(b0, b1, b2, b3,
                          sbw + SWZ((uint32_t)(kk * 2048 + brow * 128 +
                                               (2 * ntp + bsel) * 16)));
                mma16816(acc[2 * ntp + 0], a0, a1, a2, a3, b0, b1);
                mma16816(acc[2 * ntp + 1], a0, a1, a2, a3, b2, b3);
            }
        }
        __syncthreads();
    }

    // ---- Phase C: write g_hf; dots from f32 accumulators; tables ----
    const int rlo = i0 + wid * 16 + qrow;
#pragma unroll
    for (int nt = 0; nt < 8; nt++) {
        const int col = n0 + nt * 8 + qcol;
        __half2 lo = __floats2half2_rn(acc[nt][0], acc[nt][1]);
        __half2 hi = __floats2half2_rn(acc[nt][2], acc[nt][3]);
        *(uint32_t*)&g_hf[(size_t)rlo * FOUT + col] = *(uint32_t*)&lo;
        *(uint32_t*)&g_hf[(size_t)(rlo + 8) * FOUT + col] = *(uint32_t*)&hi;
    }
    {
        const float* as = a_src + head * 64;
        const float* ad = a_dst + head * 64;
        float s0 = 0.f, s1 = 0.f, d0 = 0.f, d1 = 0.f;
#pragma unroll
        for (int nt = 0; nt < 8; nt++) {
            int c = nt * 8 + qcol;
            float2 av = *(const float2*)&as[c];
            float2 dv = *(const float2*)&ad[c];
            s0 = fmaf(acc[nt][0], av.x, s0); s0 = fmaf(acc[nt][1], av.y, s0);
            s1 = fmaf(acc[nt][2], av.x, s1); s1 = fmaf(acc[nt][3], av.y, s1);
            d0 = fmaf(acc[nt][0], dv.x, d0); d0 = fmaf(acc[nt][1], dv.y, d0);
            d1 = fmaf(acc[nt][2], dv.x, d1); d1 = fmaf(acc[nt][3], dv.y, d1);
        }
        s0 += __shfl_xor_sync(0xFFFFFFFFu, s0, 1);
        s0 += __shfl_xor_sync(0xFFFFFFFFu, s0, 2);
        s1 += __shfl_xor_sync(0xFFFFFFFFu, s1, 1);
        s1 += __shfl_xor_sync(0xFFFFFFFFu, s1, 2);
        d0 += __shfl_xor_sync(0xFFFFFFFFu, d0, 1);
        d0 += __shfl_xor_sync(0xFFFFFFFFu, d0, 2);
        d1 += __shfl_xor_sync(0xFFFFFFFFu, d1, 1);
        d1 += __shfl_xor_sync(0xFFFFFFFFu, d1, 2);
        if ((lane & 3) == 0) {
            store_tables(head, rlo, s0, d0);
            store_tables(head, rlo + 8, s1, d1);
        }
    }
}

// ---------------------------------------------------------------------------
// Kernel 2: HMMA aggregation. w' = bit * max(Q, R*Q2). B double buffer 2x16KB.
// Z via ones-mma on f16 pair-sums (1 per 2 kk).
// ---------------------------------------------------------------------------
extern __shared__ unsigned char dsm[];

__global__ void __launch_bounds__(256, 2)
aggregate_kernel(const float* __restrict__ bias, float* __restrict__ out) {
    const int tid  = threadIdx.x;
    const int lane = tid & 31;
    const int wid  = tid >> 5;
    const int head = blockIdx.y;
    const int i0   = blockIdx.x * BI;
    const uint32_t sb = smem_u32(dsm);

    uint32_t bst[4];
    int jr[4], sg[4];
#pragma unroll
    for (int u = 0; u < 4; u++) {
        int unit = tid + u * 256;
        jr[u] = unit >> 3; sg[u] = unit & 7;
        bst[u] = SWZ((uint32_t)(jr[u] * 128 + sg[u] * 16));
    }

    const int brow = (lane & 7) + ((lane >> 3) & 1) * 8;
    const int bsel = (lane >> 4) & 1;
    const int qrow = lane >> 2;
    const int qcol = (lane & 3) * 2;

    int rows[2];
    uint32_t Rh[2];
#pragma unroll
    for (int r4 = 0; r4 < 2; r4++) {
        rows[r4] = wid * 16 + r4 * 8 + qrow;
        Rh[r4] = splat16(__half_as_ushort(g_RT[head * NN + i0 + rows[r4]]));
    }

    float acc[8][4];
#pragma unroll
    for (int nt = 0; nt < 8; nt++)
#pragma unroll
        for (int c = 0; c < 4; c++) acc[nt][c] = 0.f;
    float zc[4] = {0.f, 0.f, 0.f, 0.f};
    const uint32_t ONES = 0x3C003C00u;

#pragma unroll
    for (int u = 0; u < 4; u++)
        cp_async16(sb + bst[u], &g_hf[(size_t)jr[u] * FOUT + head * 64 + sg[u] * 8]);
    cp_commit();

    uint4 mrow[2];
#pragma unroll
    for (int r4 = 0; r4 < 2; r4++)
        mrow[r4] = *(const uint4*)&g_adjb[(size_t)(i0 + rows[r4]) * NWORDS];

    const uint32_t* Qsw  = &g_Qsw [head * NBLK64 * 32];
    const uint32_t* Q2sw = &g_Q2sw[head * NBLK64 * 32];
    const int moff = (lane & 3) * 4;

    for (int t = 0; t < NCHUNK; t++) {
        const int b = t & 1;
        const int j0 = t * BJ;
        const uint32_t bbuf = sb + (b ? 16384u : 0u);

        cp_wait_all();
        __syncthreads();

        {
            const int tn = (t + 1 < NCHUNK) ? t + 1 : t;
            const int jn = tn * BJ;
            const uint32_t obuf = sb + (b ? 0u : 16384u);
#pragma unroll
            for (int u = 0; u < 4; u++)
                cp_async16(obuf + bst[u],
                           &g_hf[(size_t)(jn + jr[u]) * FOUT + head * 64 + sg[u] * 8]);
            cp_commit();
        }
        uint32_t cm[2][4];
#pragma unroll
        for (int r4 = 0; r4 < 2; r4++) {
            cm[r4][0] = mrow[r4].x; cm[r4][1] = mrow[r4].y;
            cm[r4][2] = mrow[r4].z; cm[r4][3] = mrow[r4].w;
        }
        {
            const int tn = (t + 1 < NCHUNK) ? t + 1 : t;
#pragma unroll
            for (int r4 = 0; r4 < 2; r4++)
                mrow[r4] = *(const uint4*)&g_adjb[(size_t)(i0 + rows[r4]) * NWORDS + tn * 4];
        }

        uint32_t zp[4];
#pragma unroll
        for (int b64 = 0; b64 < 2; b64++) {
            const int base = ((j0 >> 6) + b64) * 32;
            const uint4 Qa4  = *(const uint4*)&Qsw [base + moff];
            const uint4 Qb4  = *(const uint4*)&Qsw [base + 16 + moff];
            const uint4 Q2a4 = *(const uint4*)&Q2sw[base + moff];
            const uint4 Q2b4 = *(const uint4*)&Q2sw[base + 16 + moff];
            uint32_t QaA[4]  = {Qa4.x, Qa4.y, Qa4.z, Qa4.w};
            uint32_t QbA[4]  = {Qb4.x, Qb4.y, Qb4.z, Qb4.w};
            uint32_t Q2aA[4] = {Q2a4.x, Q2a4.y, Q2a4.z, Q2a4.w};
            uint32_t Q2bA[4] = {Q2b4.x, Q2b4.y, Q2b4.z, Q2b4.w};

#pragma unroll
            for (int k4 = 0; k4 < 4; k4++) {
                const int kk = b64 * 4 + k4;
                const uint32_t Qa = QaA[k4], Qb = QbA[k4];
                const uint32_t Q2a = Q2aA[k4], Q2b = Q2bA[k4];
                const int shb = (kk & 1) << 4;

                uint32_t a[4];
#pragma unroll
                for (int r4 = 0; r4 < 2; r4++) {
                    const uint32_t Wm = cm[r4][kk >> 1];
                    uint32_t t0 = bfe1s(Wm, qcol + shb);
                    uint32_t t1 = bfe1s(Wm, qcol + shb + 1);
                    a[r4] = hmax2_(Qa, hmul2_(Rh[r4], Q2a)) & lop_mix(t0, t1);
                    uint32_t t2 = bfe1s(Wm, qcol + shb + 8);
                    uint32_t t3 = bfe1s(Wm, qcol + shb + 9);
                    a[r4 + 2] = hmax2_(Qb, hmul2_(Rh[r4], Q2b)) & lop_mix(t2, t3);
                }
                // Z: f16 pair-accumulate across 2 kk, one ones-mma per pair
                if ((kk & 1) == 0) {
                    zp[0] = a[0]; zp[1] = a[1]; zp[2] = a[2]; zp[3] = a[3];
                } else {
                    zp[0] = hadd2_(zp[0], a[0]); zp[1] = hadd2_(zp[1], a[1]);
                    zp[2] = hadd2_(zp[2], a[2]); zp[3] = hadd2_(zp[3], a[3]);
                    mma16816(zc, zp[0], zp[1], zp[2], zp[3], ONES, ONES);
                }
#pragma unroll
                for (int ntp = 0; ntp < 4; ntp++) {
                    uint32_t b0, b1, b2, b3;
                    ldsm_x4_t(b0, b1, b2, b3,
                              bbuf + SWZ((uint32_t)(kk * 2048 + brow * 128 +
                                                    (2 * ntp + bsel) * 16)));
                    mma16816(acc[2 * ntp + 0], a[0], a[1], a[2], a[3], b0, b1);
                    mma16816(acc[2 * ntp + 1], a[0], a[1], a[2], a[3], b2, b3);
                }
            }
        }
    }

    const float izlo = __frcp_rn(zc[0]);
    const float izhi = __frcp_rn(zc[2]);
    const int rlo = i0 + wid * 16 + qrow;
#pragma unroll
    for (int nt = 0; nt < 8; nt++) {
        const int col = head * 64 + nt * 8 + qcol;
        const float2 bv = *(const float2*)&bias[col];
        float2 o0, o1;
        o0.x = fmaf(acc[nt][0], izlo, bv.x);
        o0.y = fmaf(acc[nt][1], izlo, bv.y);
        o1.x = fmaf(acc[nt][2], izhi, bv.x);
        o1.y = fmaf(acc[nt][3], izhi, bv.y);
        *(float2*)&out[(size_t)rlo * FOUT + col] = o0;
        *(float2*)&out[(size_t)(rlo + 8) * FOUT + col] = o1;
    }
}

// ---------------------------------------------------------------------------
extern "C" void kernel_launch(void* const* d_in, const int* in_sizes, int n_in,
                              void* d_out, int out_size) {
    const float* x     = (const float*)d_in[0];
    const int*   adj   = (const int*)  d_in[1];
    const float* W     = (const float*)d_in[2];
    const float* a_src = (const float*)d_in[3];
    const float* a_dst = (const float*)d_in[4];
    const float* bias  = (const float*)d_in[5];
    float* out = (float*)d_out;

    transform_kernel<<<dim3(NN / 128, HEADS), 256>>>(x, W, adj, a_src, a_dst);
    aggregate_kernel<<<dim3(NN / BI, HEADS), 256, 32768>>>(bias, out);
}

// round 15
// speedup vs baseline: 1.2691x; 1.2691x over previous
#include <cuda_runtime.h>
#include <cuda_fp16.h>
#include <cstdint>

// ============================================================================
// SpatialGAT on GB300 — round 15: best-measured assembly
//   pack (ballot, separate) + transform (inline W cast + fused dots)
//   + aggregate (round-9 inner: mask2 selects, per-kk ones-mma, P-drop)
//
// w'_ij = bit_ij * max(Q_j, R_i*Q2_j), R_i = exp(-0.8 s_i)  (row-scale inv.)
// ============================================================================

#define NN      8192
#define FOUT    256
#define FIN     256
#define HEADS   4
#define NEG_SLOPE 0.2f
#define BI      128
#define BJ      128
#define NCHUNK  (NN / BJ)
#define NWORDS  (NN / 32)
#define NBLK64  (NN / 64)

__device__ __half   g_hf[NN * FOUT];
__device__ __half   g_RT[HEADS * NN];
__device__ uint32_t g_Qsw [HEADS * NBLK64 * 32];
__device__ uint32_t g_Q2sw[HEADS * NBLK64 * 32];
__device__ unsigned g_adjb[NN * NWORDS];

// ---------------------------------------------------------------------------
__device__ __forceinline__ uint32_t smem_u32(const void* p) {
    uint32_t a;
    asm("{ .reg .u64 t; cvta.to.shared.u64 t, %1; cvt.u32.u64 %0, t; }"
        : "=r"(a) : "l"(p));
    return a;
}
__device__ __forceinline__ uint32_t hmul2_(uint32_t a, uint32_t b) {
    uint32_t d; asm("mul.f16x2 %0, %1, %2;" : "=r"(d) : "r"(a), "r"(b)); return d;
}
__device__ __forceinline__ uint32_t hmax2_(uint32_t a, uint32_t b) {
    uint32_t d; asm("max.f16x2 %0, %1, %2;" : "=r"(d) : "r"(a), "r"(b)); return d;
}
__device__ __forceinline__ uint32_t splat16(unsigned short h) {
    uint32_t r; asm("mov.b32 %0, {%1, %1};" : "=r"(r) : "h"(h)); return r;
}
__device__ __forceinline__ uint32_t mask2(uint32_t bits) {
    return ((bits & 1u) ? 0x0000FFFFu : 0u) | ((bits & 2u) ? 0xFFFF0000u : 0u);
}
__device__ __forceinline__ void ldsm_x4(uint32_t& r0, uint32_t& r1, uint32_t& r2,
                                        uint32_t& r3, uint32_t addr) {
    asm volatile("ldmatrix.sync.aligned.m8n8.x4.shared.b16 {%0,%1,%2,%3}, [%4];"
                 : "=r"(r0), "=r"(r1), "=r"(r2), "=r"(r3) : "r"(addr));
}
__device__ __forceinline__ void ldsm_x4_t(uint32_t& r0, uint32_t& r1, uint32_t& r2,
                                          uint32_t& r3, uint32_t addr) {
    asm volatile("ldmatrix.sync.aligned.m8n8.x4.trans.shared.b16 {%0,%1,%2,%3}, [%4];"
                 : "=r"(r0), "=r"(r1), "=r"(r2), "=r"(r3) : "r"(addr));
}
__device__ __forceinline__ void mma16816(float* c, uint32_t a0, uint32_t a1,
                                         uint32_t a2, uint32_t a3,
                                         uint32_t b0, uint32_t b1) {
    asm volatile(
        "mma.sync.aligned.m16n8k16.row.col.f32.f16.f16.f32 "
        "{%0,%1,%2,%3}, {%4,%5,%6,%7}, {%8,%9}, {%0,%1,%2,%3};"
        : "+f"(c[0]), "+f"(c[1]), "+f"(c[2]), "+f"(c[3])
        : "r"(a0), "r"(a1), "r"(a2), "r"(a3), "r"(b0), "r"(b1));
}
__device__ __forceinline__ void cp_async16(uint32_t dst, const void* src) {
    unsigned long long g;
    asm("cvta.to.global.u64 %0, %1;" : "=l"(g) : "l"(src));
    asm volatile("cp.async.ca.shared.global [%0], [%1], 16;" :: "r"(dst), "l"(g));
}
__device__ __forceinline__ void cp_commit() {
    asm volatile("cp.async.commit_group;" ::: "memory");
}
__device__ __forceinline__ void cp_wait_all() {
    asm volatile("cp.async.wait_group 0;" ::: "memory");
}
#define SWZ(off) ((off) ^ (((off) >> 3) & 0x70))

// ---------------------------------------------------------------------------
// pack adj via ballot. Warp = 8 words (256 ints); block = 64 words.
// grid = NN*NWORDS/64 = 32768 blocks.
// ---------------------------------------------------------------------------
__global__ void __launch_bounds__(256) pack_kernel(const int* __restrict__ adj) {
    const int gw = (blockIdx.x * 256 + threadIdx.x) >> 5;
    const int lane = threadIdx.x & 31;
    const size_t base = (size_t)gw * 256;
    const int* p = adj + base;
    int v[8];
#pragma unroll
    for (int it = 0; it < 8; it++) v[it] = p[it * 32 + lane];
    unsigned w[8];
#pragma unroll
    for (int it = 0; it < 8; it++) w[it] = __ballot_sync(0xFFFFFFFFu, v[it] != 0);
    if (lane == 0) {
        *(uint4*)&g_adjb[base / 32]     = make_uint4(w[0], w[1], w[2], w[3]);
        *(uint4*)&g_adjb[base / 32 + 4] = make_uint4(w[4], w[5], w[6], w[7]);
    }
}

// ---------------------------------------------------------------------------
// helper: table stores for node n, head h
// ---------------------------------------------------------------------------
__device__ __forceinline__ void store_tables(int h, int n, float s, float d) {
    g_RT[h * NN + n] = __float2half_rn(expf(-0.8f * s));
    int blk = n >> 6, c = n & 63;
    int kk = c >> 4, wi = c & 15;
    int m2 = wi >> 1, hs = wi & 1;
    size_t widx = ((size_t)(h * NBLK64 + blk) * 32 + m2 * 4 + kk) * 2 + hs;
    ((__half*)g_Qsw )[widx] = __float2half_rn(expf(d));
    ((__half*)g_Q2sw)[widx] = __float2half_rn(expf(NEG_SLOPE * d));
}

// ---------------------------------------------------------------------------
// transform: h = x @ W via HMMA (x, W converted inline) + fused logit dots.
// grid (64, 4), 256 threads.
// ---------------------------------------------------------------------------
__global__ void __launch_bounds__(256) transform_kernel(
        const float* __restrict__ x, const float* __restrict__ W,
        const float* __restrict__ a_src, const float* __restrict__ a_dst) {
    __shared__ __align__(16) unsigned char ts[16384 + 8192];
    const uint32_t sbx = smem_u32(ts);
    const uint32_t sbw = sbx + 16384;
    const int tid = threadIdx.x;
    const int lane = tid & 31, wid = tid >> 5;
    const int i0 = blockIdx.x * 128;
    const int head = blockIdx.y;
    const int n0 = head * 64;

    const int arow = (lane & 7) + ((lane >> 3) & 1) * 8;
    const uint32_t a_base = (uint32_t)((wid * 16 + arow) * 128 + (lane >> 4) * 16);
    const int brow = (lane & 7) + ((lane >> 3) & 1) * 8;
    const int bsel = (lane >> 4) & 1;
    const int qrow = lane >> 2, qcol = (lane & 3) * 2;

    float acc[8][4];
#pragma unroll
    for (int nt = 0; nt < 8; nt++)
#pragma unroll
        for (int c = 0; c < 4; c++) acc[nt][c] = 0.f;

    for (int kc = 0; kc < 4; kc++) {
        const int k0 = kc * 64;
#pragma unroll
        for (int u = 0; u < 4; u++) {
            int unit = tid + u * 256;
            int row = unit >> 3, seg = unit & 7;
            const float* xp = &x[(size_t)(i0 + row) * FIN + k0 + seg * 8];
            float4 f0 = *(const float4*)xp;
            float4 f1 = *(const float4*)(xp + 4);
            __half2 h0 = __floats2half2_rn(f0.x, f0.y);
            __half2 h1 = __floats2half2_rn(f0.z, f0.w);
            __half2 h2 = __floats2half2_rn(f1.x, f1.y);
            __half2 h3 = __floats2half2_rn(f1.z, f1.w);
            uint4 v;
            v.x = *(uint32_t*)&h0; v.y = *(uint32_t*)&h1;
            v.z = *(uint32_t*)&h2; v.w = *(uint32_t*)&h3;
            *(uint4*)(ts + SWZ((uint32_t)(row * 128 + seg * 16))) = v;
        }
#pragma unroll
        for (int u = 0; u < 2; u++) {
            int unit = tid + u * 256;
            int row = unit >> 3, seg = unit & 7;
            const float* wp = &W[(size_t)(k0 + row) * FOUT + n0 + seg * 8];
            float4 f0 = *(const float4*)wp;
            float4 f1 = *(const float4*)(wp + 4);
            __half2 h0 = __floats2half2_rn(f0.x, f0.y);
            __half2 h1 = __floats2half2_rn(f0.z, f0.w);
            __half2 h2 = __floats2half2_rn(f1.x, f1.y);
            __half2 h3 = __floats2half2_rn(f1.z, f1.w);
            uint4 v;
            v.x = *(uint32_t*)&h0; v.y = *(uint32_t*)&h1;
            v.z = *(uint32_t*)&h2; v.w = *(uint32_t*)&h3;
            *(uint4*)(ts + 16384 + SWZ((uint32_t)(row * 128 + seg * 16))) = v;
        }
        __syncthreads();
#pragma unroll
        for (int kk = 0; kk < 4; kk++) {
            uint32_t a0, a1, a2, a3;
            ldsm_x4(a0, a1, a2, a3, sbx + SWZ(a_base + kk * 32));
#pragma unroll
            for (int ntp = 0; ntp < 4; ntp++) {
                uint32_t b0, b1, b2, b3;
                ldsm_x4_t(b0, b1, b2, b3,
                          sbw + SWZ((uint32_t)(kk * 2048 + brow * 128 +
                                               (2 * ntp + bsel) * 16)));
                mma16816(acc[2 * ntp + 0], a0, a1, a2, a3, b0, b1);
                mma16816(acc[2 * ntp + 1], a0, a1, a2, a3, b2, b3);
            }
        }
        __syncthreads();
    }

    const int rlo = i0 + wid * 16 + qrow;
#pragma unroll
    for (int nt = 0; nt < 8; nt++) {
        const int col = n0 + nt * 8 + qcol;
        __half2 lo = __floats2half2_rn(acc[nt][0], acc[nt][1]);
        __half2 hi = __floats2half2_rn(acc[nt][2], acc[nt][3]);
        *(uint32_t*)&g_hf[(size_t)rlo * FOUT + col] = *(uint32_t*)&lo;
        *(uint32_t*)&g_hf[(size_t)(rlo + 8) * FOUT + col] = *(uint32_t*)&hi;
    }
    {
        const float* as = a_src + head * 64;
        const float* ad = a_dst + head * 64;
        float s0 = 0.f, s1 = 0.f, d0 = 0.f, d1 = 0.f;
#pragma unroll
        for (int nt = 0; nt < 8; nt++) {
            int c = nt * 8 + qcol;
            float2 av = *(const float2*)&as[c];
            float2 dv = *(const float2*)&ad[c];
            s0 = fmaf(acc[nt][0], av.x, s0); s0 = fmaf(acc[nt][1], av.y, s0);
            s1 = fmaf(acc[nt][2], av.x, s1); s1 = fmaf(acc[nt][3], av.y, s1);
            d0 = fmaf(acc[nt][0], dv.x, d0); d0 = fmaf(acc[nt][1], dv.y, d0);
            d1 = fmaf(acc[nt][2], dv.x, d1); d1 = fmaf(acc[nt][3], dv.y, d1);
        }
        s0 += __shfl_xor_sync(0xFFFFFFFFu, s0, 1);
        s0 += __shfl_xor_sync(0xFFFFFFFFu, s0, 2);
        s1 += __shfl_xor_sync(0xFFFFFFFFu, s1, 1);
        s1 += __shfl_xor_sync(0xFFFFFFFFu, s1, 2);
        d0 += __shfl_xor_sync(0xFFFFFFFFu, d0, 1);
        d0 += __shfl_xor_sync(0xFFFFFFFFu, d0, 2);
        d1 += __shfl_xor_sync(0xFFFFFFFFu, d1, 1);
        d1 += __shfl_xor_sync(0xFFFFFFFFu, d1, 2);
        if ((lane & 3) == 0) {
            store_tables(head, rlo, s0, d0);
            store_tables(head, rlo + 8, s1, d1);
        }
    }
}

// ---------------------------------------------------------------------------
// aggregate: round-9 inner loop (mask2 selects, per-kk ones-mma) + P-drop.
// ---------------------------------------------------------------------------
extern __shared__ unsigned char dsm[];

__global__ void __launch_bounds__(256, 2)
aggregate_kernel(const float* __restrict__ bias, float* __restrict__ out) {
    const int tid  = threadIdx.x;
    const int lane = tid & 31;
    const int wid  = tid >> 5;
    const int head = blockIdx.y;
    const int i0   = blockIdx.x * BI;
    const uint32_t sb = smem_u32(dsm);

    uint32_t bst[4];
    int jr[4], sg[4];
#pragma unroll
    for (int u = 0; u < 4; u++) {
        int unit = tid + u * 256;
        jr[u] = unit >> 3; sg[u] = unit & 7;
        bst[u] = SWZ((uint32_t)(jr[u] * 128 + sg[u] * 16));
    }

    const int brow = (lane & 7) + ((lane >> 3) & 1) * 8;
    const int bsel = (lane >> 4) & 1;
    const int qrow = lane >> 2;
    const int qcol = (lane & 3) * 2;

    int rows[2];
    uint32_t Rh[2];
#pragma unroll
    for (int r4 = 0; r4 < 2; r4++) {
        rows[r4] = wid * 16 + r4 * 8 + qrow;
        Rh[r4] = splat16(__half_as_ushort(g_RT[head * NN + i0 + rows[r4]]));
    }

    float acc[8][4];
#pragma unroll
    for (int nt = 0; nt < 8; nt++)
#pragma unroll
        for (int c = 0; c < 4; c++) acc[nt][c] = 0.f;
    float zc[4] = {0.f, 0.f, 0.f, 0.f};
    const uint32_t ONES = 0x3C003C00u;

#pragma unroll
    for (int u = 0; u < 4; u++)
        cp_async16(sb + bst[u], &g_hf[(size_t)jr[u] * FOUT + head * 64 + sg[u] * 8]);
    cp_commit();

    uint4 mrow[2];
#pragma unroll
    for (int r4 = 0; r4 < 2; r4++)
        mrow[r4] = *(const uint4*)&g_adjb[(size_t)(i0 + rows[r4]) * NWORDS];

    const uint32_t* Qsw  = &g_Qsw [head * NBLK64 * 32];
    const uint32_t* Q2sw = &g_Q2sw[head * NBLK64 * 32];
    const int moff = (lane & 3) * 4;

    for (int t = 0; t < NCHUNK; t++) {
        const int b = t & 1;
        const int j0 = t * BJ;
        const uint32_t bbuf = sb + (b ? 16384u : 0u);

        cp_wait_all();
        __syncthreads();

        {
            const int tn = (t + 1 < NCHUNK) ? t + 1 : t;
            const int jn = tn * BJ;
            const uint32_t obuf = sb + (b ? 0u : 16384u);
#pragma unroll
            for (int u = 0; u < 4; u++)
                cp_async16(obuf + bst[u],
                           &g_hf[(size_t)(jn + jr[u]) * FOUT + head * 64 + sg[u] * 8]);
            cp_commit();
        }
        uint32_t cm[2][4];
#pragma unroll
        for (int r4 = 0; r4 < 2; r4++) {
            cm[r4][0] = mrow[r4].x; cm[r4][1] = mrow[r4].y;
            cm[r4][2] = mrow[r4].z; cm[r4][3] = mrow[r4].w;
        }
        {
            const int tn = (t + 1 < NCHUNK) ? t + 1 : t;
#pragma unroll
            for (int r4 = 0; r4 < 2; r4++)
                mrow[r4] = *(const uint4*)&g_adjb[(size_t)(i0 + rows[r4]) * NWORDS + tn * 4];
        }

#pragma unroll
        for (int b64 = 0; b64 < 2; b64++) {
            const int base = ((j0 >> 6) + b64) * 32;
            const uint4 Qa4  = *(const uint4*)&Qsw [base + moff];
            const uint4 Qb4  = *(const uint4*)&Qsw [base + 16 + moff];
            const uint4 Q2a4 = *(const uint4*)&Q2sw[base + moff];
            const uint4 Q2b4 = *(const uint4*)&Q2sw[base + 16 + moff];
            uint32_t QaA[4]  = {Qa4.x, Qa4.y, Qa4.z, Qa4.w};
            uint32_t QbA[4]  = {Qb4.x, Qb4.y, Qb4.z, Qb4.w};
            uint32_t Q2aA[4] = {Q2a4.x, Q2a4.y, Q2a4.z, Q2a4.w};
            uint32_t Q2bA[4] = {Q2b4.x, Q2b4.y, Q2b4.z, Q2b4.w};

#pragma unroll
            for (int k4 = 0; k4 < 4; k4++) {
                const int kk = b64 * 4 + k4;
                const uint32_t Qa = QaA[k4], Qb = QbA[k4];
                const uint32_t Q2a = Q2aA[k4], Q2b = Q2bA[k4];
                const uint32_t sh = ((kk & 1) << 4) + qcol;

                uint32_t a[4];
#pragma unroll
                for (int r4 = 0; r4 < 2; r4++) {
                    const uint32_t Wm = cm[r4][kk >> 1];
                    const uint32_t ba = Wm >> sh;
                    a[r4]     = hmax2_(Qa, hmul2_(Rh[r4], Q2a)) & mask2(ba);
                    a[r4 + 2] = hmax2_(Qb, hmul2_(Rh[r4], Q2b)) & mask2(ba >> 8);
                }
                mma16816(zc, a[0], a[1], a[2], a[3], ONES, ONES);
#pragma unroll
                for (int ntp = 0; ntp < 4; ntp++) {
                    uint32_t b0, b1, b2, b3;
                    ldsm_x4_t(b0, b1, b2, b3,
                              bbuf + SWZ((uint32_t)(kk * 2048 + brow * 128 +
                                                    (2 * ntp + bsel) * 16)));
                    mma16816(acc[2 * ntp + 0], a[0], a[1], a[2], a[3], b0, b1);
                    mma16816(acc[2 * ntp + 1], a[0], a[1], a[2], a[3], b2, b3);
                }
            }
        }
    }

    const float izlo = __frcp_rn(zc[0]);
    const float izhi = __frcp_rn(zc[2]);
    const int rlo = i0 + wid * 16 + qrow;
#pragma unroll
    for (int nt = 0; nt < 8; nt++) {
        const int col = head * 64 + nt * 8 + qcol;
        const float2 bv = *(const float2*)&bias[col];
        float2 o0, o1;
        o0.x = fmaf(acc[nt][0], izlo, bv.x);
        o0.y = fmaf(acc[nt][1], izlo, bv.y);
        o1.x = fmaf(acc[nt][2], izhi, bv.x);
        o1.y = fmaf(acc[nt][3], izhi, bv.y);
        *(float2*)&out[(size_t)rlo * FOUT + col] = o0;
        *(float2*)&out[(size_t)(rlo + 8) * FOUT + col] = o1;
    }
}

// ---------------------------------------------------------------------------
extern "C" void kernel_launch(void* const* d_in, const int* in_sizes, int n_in,
                              void* d_out, int out_size) {
    const float* x     = (const float*)d_in[0];
    const int*   adj   = (const int*)  d_in[1];
    const float* W     = (const float*)d_in[2];
    const float* a_src = (const float*)d_in[3];
    const float* a_dst = (const float*)d_in[4];
    const float* bias  = (const float*)d_in[5];
    float* out = (float*)d_out;

    pack_kernel<<<(NN * NWORDS) / 64, 256>>>(adj);
    transform_kernel<<<dim3(NN / 128, HEADS), 256>>>(x, W, a_src, a_dst);
    aggregate_kernel<<<dim3(NN / BI, HEADS), 256, 32768>>>(bias, out);
}